// round 7
// baseline (speedup 1.0000x reference)
#include <cuda_runtime.h>
#include <cuda_fp16.h>

// ---------------- smem layout (u32 units) ----------------
#define OFF_H1  2304                 // xs: 64x72 halves = 2304 u32
#define SMEM_U32 10752               // h1: 64x264 halves = 8448 u32
#define SMEM_BYTES (SMEM_U32 * 4)    // 43008

#define NPREP 48

// device scratch
__device__ unsigned g_A1pack[10240];   // GEMM1 B frags (fp16x2): [A1 | Q], 320 cols
__device__ unsigned g_W2pack[16384];   // GEMM2 B frags (fp16x2)
__device__ float    g_c1[256];
__device__ float    g_c0[1];
__device__ unsigned g_ready = 0;
__device__ unsigned g_done  = 0;

__device__ __forceinline__ unsigned pack_h2(float a, float b) {
    __half2 h = __floats2half2_rn(a, b);
    return *(unsigned*)&h;
}
__device__ __forceinline__ void mma_fp16(float* c, unsigned a0, unsigned a1,
                                         unsigned a2, unsigned a3,
                                         unsigned b0, unsigned b1) {
    asm volatile("mma.sync.aligned.m16n8k16.row.col.f32.f16.f16.f32 "
                 "{%0,%1,%2,%3}, {%4,%5,%6,%7}, {%8,%9}, {%0,%1,%2,%3};"
                 : "+f"(c[0]), "+f"(c[1]), "+f"(c[2]), "+f"(c[3])
                 : "r"(a0), "r"(a1), "r"(a2), "r"(a3), "r"(b0), "r"(b1));
}
__device__ __forceinline__ void ldsm_x4(unsigned& r0, unsigned& r1, unsigned& r2,
                                        unsigned& r3, unsigned saddr) {
    asm volatile("ldmatrix.sync.aligned.m8n8.x4.shared.b16 {%0,%1,%2,%3}, [%4];"
                 : "=r"(r0), "=r"(r1), "=r"(r2), "=r"(r3) : "r"(saddr));
}

// =============== prep phase (run by blocks 0..47 of the fused kernel) ===============
__device__ void prep_body(int b, int tid, float* shm,
                          const float* __restrict__ emb, const float* __restrict__ Wc,
                          const float* __restrict__ bc,  const float* __restrict__ Wf,
                          const float* __restrict__ bf,  const float* __restrict__ W1,
                          const float* __restrict__ b1,  const float* __restrict__ W2) {
    if (b < 32) {
        float* dv   = shm;
        float* base = shm + 1024;
        float* WcA  = shm + 2048;
        float* WcB  = shm + 2080;
        for (int e = tid; e < 1024; e += 256) {
            int f = e >> 4, d = e & 15;
            if (f < 62) { dv[e] = emb[f * 32 + 16 + d] - emb[f * 32 + d]; base[e] = emb[f * 32 + d]; }
            else        { dv[e] = 0.f; base[e] = bc[e - 992]; }
        }
        if (tid < 32) { WcA[tid] = Wc[tid * 2]; WcB[tid] = Wc[tid * 2 + 1]; }
        __syncthreads();

        int w = tid >> 5, l = tid & 31;
        int j = b * 8 + w;
        const float4* wrow = (const float4*)(W1 + j * 1024);
        float cp = 0.f;
        #pragma unroll
        for (int r = 0; r < 8; r++) {
            int q = l + 32 * r;
            float4 wv = __ldg(wrow + q);
            int e0 = q * 4;
            float4 dvv = *(const float4*)(dv + e0);
            float4 bsv = *(const float4*)(base + e0);
            float pd = wv.x * dvv.x + wv.y * dvv.y + wv.z * dvv.z + wv.w * dvv.w;
            cp += wv.x * bsv.x + wv.y * bsv.y + wv.z * bsv.z + wv.w * bsv.w;
            pd += __shfl_xor_sync(0xffffffffu, pd, 1);
            pd += __shfl_xor_sync(0xffffffffu, pd, 2);
            float s62 = 0.f, s63 = 0.f;
            if (r == 7) {
                float p0 = 0.f, p1 = 0.f;
                if (l >= 24) {
                    int m0 = e0 - 992;
                    float4 wa = *(const float4*)(WcA + m0);
                    float4 wb = *(const float4*)(WcB + m0);
                    p0 = wv.x * wa.x + wv.y * wa.y + wv.z * wa.z + wv.w * wa.w;
                    p1 = wv.x * wb.x + wv.y * wb.y + wv.z * wb.z + wv.w * wb.w;
                }
                p0 += __shfl_xor_sync(0xffffffffu, p0, 1);
                p0 += __shfl_xor_sync(0xffffffffu, p0, 2);
                p0 += __shfl_xor_sync(0xffffffffu, p0, 4);
                p1 += __shfl_xor_sync(0xffffffffu, p1, 1);
                p1 += __shfl_xor_sync(0xffffffffu, p1, 2);
                p1 += __shfl_xor_sync(0xffffffffu, p1, 4);
                s62 = p0; s63 = p1;
            }
            float vnext = __shfl_sync(0xffffffffu, pd, (l + 4) & 31);
            int gidx = l >> 2;
            if ((l & 7) == 0) {
                float e0v = pd, e1v = vnext;
                if (r == 7 && gidx == 6) { e0v = s62; e1v = s63; }
                int p = (gidx >> 1) + 4 * r;
                int kt = p >> 3, reg = (p >> 2) & 1, tgx = p & 3;
                g_A1pack[((kt * 40 + (j >> 3)) * 32 + (j & 7) * 4 + tgx) * 2 + reg] =
                    pack_h2(e0v, e1v);
            }
        }
        #pragma unroll
        for (int o = 16; o; o >>= 1) cp += __shfl_xor_sync(0xffffffffu, cp, o);
        if (l == 0) g_c1[j] = cp + b1[j];

    } else if (b < 40) {
        int c = b - 32;
        float* w2s = shm;
        for (int q = tid; q < 1024; q += 256) {
            int row = q >> 3, f4 = q & 7;
            *(float4*)(w2s + row * 32 + f4 * 4) =
                __ldg((const float4*)(W2 + row * 256 + c * 32 + f4 * 4));
        }
        __syncthreads();
        for (int e = tid; e < 2048; e += 256) {
            int reg = e & 1, l2 = (e >> 1) & 31, nt = (e >> 6) & 15, itl = e >> 10;
            int gg = l2 >> 2, tgx = l2 & 3;
            int il = itl * 16 + reg * 8 + 2 * tgx;
            int k  = nt * 8 + gg;
            g_W2pack[c * 2048 + e] = pack_h2(w2s[k * 32 + il], w2s[k * 32 + il + 1]);
        }

    } else {
        int qb = b - 40;
        float (*v)[16] = (float(*)[16])shm;
        float* u  = shm + 1024;
        float* tS = shm + 1040;
        float* sS = shm + 1104;
        float* Rs = shm + 1168;
        for (int idx = tid; idx < 1024; idx += 256) {
            int f = idx >> 4, d = idx & 15;
            float val;
            if (f < 62)       val = emb[f * 32 + 16 + d] - emb[f * 32 + d];
            else if (f == 62) val = Wc[d * 2]     + Wc[(16 + d) * 2];
            else              val = Wc[d * 2 + 1] + Wc[(16 + d) * 2 + 1];
            v[f][d] = val;
        }
        if (tid < 16) {
            float s = bc[tid] + bc[16 + tid];
            for (int f = 0; f < 62; f++) s += emb[f * 32 + tid];
            u[tid] = s;
        }
        if (tid == 0) {
            float r = 0.f;
            for (int m = 0; m < 32; m++) r += Wc[m * 2] * Wc[m * 2 + 1];
            Rs[0] = r;
        }
        __syncthreads();
        if (tid < 64) {
            float t = 0.f, s = 0.f;
            if (tid < 62) {
                #pragma unroll
                for (int d = 0; d < 16; d++) { t += emb[tid * 32 + d] * v[tid][d]; s += v[tid][d] * v[tid][d]; }
            } else {
                int jc = tid - 62;
                for (int m = 0; m < 32; m++) { float wv = Wc[m * 2 + jc]; t += bc[m] * wv; s += wv * wv; }
            }
            tS[tid] = t; sS[tid] = s;
        }
        __syncthreads();
        int e = qb * 256 + tid;
        int gc = e >> 5, p = e & 31, f0 = 2 * p;
        float q2[2];
        #pragma unroll
        for (int h = 0; h < 2; h++) {
            int fr = f0 + h;
            if (fr == gc) {
                float uv = 0.f, vv = 0.f;
                #pragma unroll
                for (int d = 0; d < 16; d++) { uv += u[d] * v[fr][d]; vv += v[fr][d] * v[fr][d]; }
                q2[h] = uv - tS[fr] + 0.5f * (vv - sS[fr]) + Wf[fr];
            } else {
                float dp = 0.f;
                #pragma unroll
                for (int d = 0; d < 16; d++) dp += v[fr][d] * v[gc][d];
                float rr = ((fr == 62 && gc == 63) || (fr == 63 && gc == 62)) ? Rs[0] : 0.f;
                q2[h] = 0.5f * (dp - rr);
            }
        }
        int kt = p >> 3, reg = (p >> 2) & 1, tgx = p & 3;
        g_A1pack[((kt * 40 + 32 + (gc >> 3)) * 32 + (gc & 7) * 4 + tgx) * 2 + reg] =
            pack_h2(q2[0], q2[1]);
        if (qb == 0 && tid == 0) {
            float uu = 0.f;
            for (int d = 0; d < 16; d++) uu += u[d] * u[d];
            float e2 = 0.f;
            for (int f = 0; f < 62; f++)
                for (int d = 0; d < 16; d++) { float ev = emb[f * 32 + d]; e2 += ev * ev; }
            for (int m = 0; m < 32; m++) e2 += bc[m] * bc[m];
            g_c0[0] = bf[0] + 0.5f * (uu - e2);
        }
    }
}

// =============== fused kernel: prep (blocks 0..47) + doorbell + main ===============
__global__ __launch_bounds__(256, 4) void deepfm_fused(
    const float* __restrict__ x,   const float* __restrict__ emb,
    const float* __restrict__ Wc,  const float* __restrict__ bc,
    const float* __restrict__ Wf,  const float* __restrict__ bf,
    const float* __restrict__ W1,  const float* __restrict__ b1,
    const float* __restrict__ W2,  const float* __restrict__ b2,
    float* __restrict__ out) {
    extern __shared__ unsigned smu[];
    __half* xs = (__half*)smu;              // [64][72]
    __half* h1 = (__half*)(smu + OFF_H1);   // [64][264]

    const int tid = threadIdx.x;
    const int bid = blockIdx.x;
    const int b0  = bid * 64;

    // ---- prep phase on first 48 blocks (dispatch-order resident in wave 1) ----
    if (bid < NPREP) {
        prep_body(bid, tid, (float*)smu, emb, Wc, bc, Wf, bf, W1, b1, W2);
        __syncthreads();                    // all prep writes done block-wide
    }
    // ---- global doorbell: release (prep) / acquire (all) ----
    if (tid == 0) {
        if (bid < NPREP) { __threadfence(); atomicAdd(&g_ready, 1u); }
        while (*(volatile unsigned*)&g_ready < (unsigned)NPREP) { }
        __threadfence();
        unsigned d = atomicAdd(&g_done, 1u);
        if (d == (unsigned)gridDim.x - 1u) {   // last block through: reset for next replay
            g_done = 0u; g_ready = 0u; __threadfence();
        }
    }
    __syncthreads();

    // ---- stage x (fp32 -> fp16) ----
    {
        int s = tid >> 2, q = tid & 3;
        const float4* xr = (const float4*)(x + (size_t)(b0 + s) * 64 + q * 16);
        float4 v0 = __ldg(xr), v1 = __ldg(xr + 1), v2 = __ldg(xr + 2), v3 = __ldg(xr + 3);
        __half2* dst = (__half2*)(xs + s * 72 + q * 16);
        dst[0] = __floats2half2_rn(v0.x, v0.y); dst[1] = __floats2half2_rn(v0.z, v0.w);
        dst[2] = __floats2half2_rn(v1.x, v1.y); dst[3] = __floats2half2_rn(v1.z, v1.w);
        dst[4] = __floats2half2_rn(v2.x, v2.y); dst[5] = __floats2half2_rn(v2.z, v2.w);
        dst[6] = __floats2half2_rn(v3.x, v3.y); dst[7] = __floats2half2_rn(v3.z, v3.w);
    }
    __syncthreads();

    const int w = tid >> 5, l = tid & 31, g = l >> 2, tg = l & 3;
    const int mh = w & 1, nq = w >> 1;
    const int lrow = l & 15, lcol = l >> 4;
    const int rbase = mh * 32;

    unsigned xs_lm0 = (unsigned)__cvta_generic_to_shared(xs + (rbase + lrow) * 72 + lcol * 8);
    unsigned xs_lm1 = xs_lm0 + 16 * 72 * 2;
    unsigned h1_lm0 = (unsigned)__cvta_generic_to_shared(h1 + (rbase + lrow) * 264 + lcol * 8);
    unsigned h1_lm1 = h1_lm0 + 16 * 264 * 2;

    // ---- GEMM1: z[64 x 320] = x @ [A1 | Q], B-frags from L2/L1 with prefetch ----
    float fmd[2][2] = {{0.f, 0.f}, {0.f, 0.f}};
    const int ntb = nq * 10;
    #pragma unroll 1
    for (int pass = 0; pass < 2; pass++) {
        int nt0 = ntb + pass * 5;
        const uint2* bbase = (const uint2*)g_A1pack + nt0 * 32 + l;
        uint2 bc_[5];
        #pragma unroll
        for (int t = 0; t < 5; t++) bc_[t] = __ldg(bbase + t * 32);

        float acc[2][5][4];
        #pragma unroll
        for (int t = 0; t < 5; t++) {
            int j0 = (nt0 + t) * 8;
            float c0v = 0.f, c1v = 0.f;
            if (j0 < 256) { float2 cc = __ldg((const float2*)(g_c1 + j0 + 2 * tg)); c0v = cc.x; c1v = cc.y; }
            acc[0][t][0] = c0v; acc[0][t][1] = c1v; acc[0][t][2] = c0v; acc[0][t][3] = c1v;
            acc[1][t][0] = c0v; acc[1][t][1] = c1v; acc[1][t][2] = c0v; acc[1][t][3] = c1v;
        }
        #pragma unroll
        for (int kt = 0; kt < 4; kt++) {
            uint2 bn_[5];
            if (kt < 3) {
                const uint2* bp = bbase + (kt + 1) * 40 * 32;
                #pragma unroll
                for (int t = 0; t < 5; t++) bn_[t] = __ldg(bp + t * 32);
            }
            unsigned am0[4], am1[4];
            ldsm_x4(am0[0], am0[1], am0[2], am0[3], xs_lm0 + kt * 32);
            ldsm_x4(am1[0], am1[1], am1[2], am1[3], xs_lm1 + kt * 32);
            #pragma unroll
            for (int t = 0; t < 5; t++) {
                mma_fp16(acc[0][t], am0[0], am0[1], am0[2], am0[3], bc_[t].x, bc_[t].y);
                mma_fp16(acc[1][t], am1[0], am1[1], am1[2], am1[3], bc_[t].x, bc_[t].y);
            }
            if (kt < 3) {
                #pragma unroll
                for (int t = 0; t < 5; t++) bc_[t] = bn_[t];
            }
        }
        #pragma unroll
        for (int t = 0; t < 5; t++) {
            int j0 = (nt0 + t) * 8;
            #pragma unroll
            for (int mt = 0; mt < 2; mt++) {
                int r0 = rbase + mt * 16 + g;
                if (j0 < 256) {
                    *(__half2*)(h1 + r0 * 264 + j0 + 2 * tg) =
                        __floats2half2_rn(fmaxf(acc[mt][t][0], 0.f), fmaxf(acc[mt][t][1], 0.f));
                    *(__half2*)(h1 + (r0 + 8) * 264 + j0 + 2 * tg) =
                        __floats2half2_rn(fmaxf(acc[mt][t][2], 0.f), fmaxf(acc[mt][t][3], 0.f));
                } else {
                    int fo = j0 - 256;
                    float2 xf0 = __half22float2(*(__half2*)(xs + r0 * 72 + fo + 2 * tg));
                    float2 xf1 = __half22float2(*(__half2*)(xs + (r0 + 8) * 72 + fo + 2 * tg));
                    fmd[mt][0] += xf0.x * acc[mt][t][0] + xf0.y * acc[mt][t][1];
                    fmd[mt][1] += xf1.x * acc[mt][t][2] + xf1.y * acc[mt][t][3];
                }
            }
        }
    }
    if (nq == 3) {   // FM output
        #pragma unroll
        for (int mt = 0; mt < 2; mt++) {
            #pragma unroll
            for (int i = 0; i < 2; i++) {
                fmd[mt][i] += __shfl_xor_sync(0xffffffffu, fmd[mt][i], 1);
                fmd[mt][i] += __shfl_xor_sync(0xffffffffu, fmd[mt][i], 2);
            }
        }
        if (tg == 0) {
            float C0 = __ldg(&g_c0[0]);
            #pragma unroll
            for (int mt = 0; mt < 2; mt++) {
                int r0 = rbase + mt * 16 + g;
                out[(size_t)(b0 + r0) * 129]     = C0 + fmd[mt][0];
                out[(size_t)(b0 + r0 + 8) * 129] = C0 + fmd[mt][1];
            }
        }
    }
    __syncthreads();   // h1 complete

    // ---- GEMM2: out[:,1:] = relu(h1 @ W2T + b2) ----
    float acc2[2][4][4];
    #pragma unroll
    for (int t = 0; t < 4; t++) {
        int k0 = nq * 32 + t * 8;
        float2 bb = __ldg((const float2*)(b2 + k0 + 2 * tg));
        acc2[0][t][0] = bb.x; acc2[0][t][1] = bb.y; acc2[0][t][2] = bb.x; acc2[0][t][3] = bb.y;
        acc2[1][t][0] = bb.x; acc2[1][t][1] = bb.y; acc2[1][t][2] = bb.x; acc2[1][t][3] = bb.y;
    }
    {
        const uint2* wbase = (const uint2*)g_W2pack + nq * 4 * 32 + l;
        uint2 wc_[4];
        #pragma unroll
        for (int t = 0; t < 4; t++) wc_[t] = __ldg(wbase + t * 32);
        #pragma unroll
        for (int it = 0; it < 16; it++) {
            uint2 wn_[4];
            if (it < 15) {
                const uint2* wp = wbase + (it + 1) * 16 * 32;
                #pragma unroll
                for (int t = 0; t < 4; t++) wn_[t] = __ldg(wp + t * 32);
            }
            unsigned aa0[4], aa1[4];
            ldsm_x4(aa0[0], aa0[1], aa0[2], aa0[3], h1_lm0 + it * 32);
            ldsm_x4(aa1[0], aa1[1], aa1[2], aa1[3], h1_lm1 + it * 32);
            #pragma unroll
            for (int t = 0; t < 4; t++) {
                mma_fp16(acc2[0][t], aa0[0], aa0[1], aa0[2], aa0[3], wc_[t].x, wc_[t].y);
                mma_fp16(acc2[1][t], aa1[0], aa1[1], aa1[2], aa1[3], wc_[t].x, wc_[t].y);
            }
            if (it < 15) {
                #pragma unroll
                for (int t = 0; t < 4; t++) wc_[t] = wn_[t];
            }
        }
    }
    #pragma unroll
    for (int mt = 0; mt < 2; mt++) {
        #pragma unroll
        for (int t = 0; t < 4; t++) {
            int k0 = nq * 32 + t * 8 + 2 * tg;
            int r0 = rbase + mt * 16 + g;
            size_t o0 = (size_t)(b0 + r0) * 129 + 1 + k0;
            size_t o1 = (size_t)(b0 + r0 + 8) * 129 + 1 + k0;
            out[o0]     = fmaxf(acc2[mt][t][0], 0.f);
            out[o0 + 1] = fmaxf(acc2[mt][t][1], 0.f);
            out[o1]     = fmaxf(acc2[mt][t][2], 0.f);
            out[o1 + 1] = fmaxf(acc2[mt][t][3], 0.f);
        }
    }
}

// ---------------- launch ----------------
extern "C" void kernel_launch(void* const* d_in, const int* in_sizes, int n_in,
                              void* d_out, int out_size) {
    const float* x   = (const float*)d_in[0];
    const float* emb = (const float*)d_in[1];
    const float* Wc  = (const float*)d_in[2];
    const float* bc  = (const float*)d_in[3];
    const float* Wf  = (const float*)d_in[4];
    const float* bf  = (const float*)d_in[5];
    const float* W1  = (const float*)d_in[6];
    const float* b1  = (const float*)d_in[7];
    const float* W2  = (const float*)d_in[8];
    const float* b2  = (const float*)d_in[9];
    float* out = (float*)d_out;

    cudaFuncSetAttribute(deepfm_fused, cudaFuncAttributeMaxDynamicSharedMemorySize, SMEM_BYTES);
    deepfm_fused<<<1024, 256, SMEM_BYTES>>>(x, emb, Wc, bc, Wf, bf, W1, b1, W2, b2, out);
}

// round 8
// speedup vs baseline: 1.0329x; 1.0329x over previous
#include <cuda_runtime.h>
#include <cuda_fp16.h>

// ---------------- smem layout (u32 units) ----------------
#define OFF_H1  2304                 // xs: 64x72 halves = 2304 u32
#define SMEM_U32 10752               // h1: 64x264 halves = 8448 u32
#define SMEM_BYTES (SMEM_U32 * 4)    // 43008

// device scratch
__device__ unsigned g_A1pack[10240];   // GEMM1 B frags (fp16x2): [A1 | Q], 320 cols
__device__ unsigned g_W2pack[16384];   // GEMM2 B frags (fp16x2)
__device__ float    g_c1[256];
__device__ float    g_c0[1];

__device__ __forceinline__ unsigned pack_h2(float a, float b) {
    __half2 h = __floats2half2_rn(a, b);
    return *(unsigned*)&h;
}
__device__ __forceinline__ void mma_fp16(float* c, unsigned a0, unsigned a1,
                                         unsigned a2, unsigned a3,
                                         unsigned b0, unsigned b1) {
    asm volatile("mma.sync.aligned.m16n8k16.row.col.f32.f16.f16.f32 "
                 "{%0,%1,%2,%3}, {%4,%5,%6,%7}, {%8,%9}, {%0,%1,%2,%3};"
                 : "+f"(c[0]), "+f"(c[1]), "+f"(c[2]), "+f"(c[3])
                 : "r"(a0), "r"(a1), "r"(a2), "r"(a3), "r"(b0), "r"(b1));
}
__device__ __forceinline__ void ldsm_x4(unsigned& r0, unsigned& r1, unsigned& r2,
                                        unsigned& r3, unsigned saddr) {
    asm volatile("ldmatrix.sync.aligned.m8n8.x4.shared.b16 {%0,%1,%2,%3}, [%4];"
                 : "=r"(r0), "=r"(r1), "=r"(r2), "=r"(r3) : "r"(saddr));
}

// =============== merged prep kernel: 48 blocks (R5/R6 proven) ===============
__global__ void prep_all(const float* __restrict__ emb, const float* __restrict__ Wc,
                         const float* __restrict__ bc,  const float* __restrict__ Wf,
                         const float* __restrict__ bf,  const float* __restrict__ W1,
                         const float* __restrict__ b1,  const float* __restrict__ W2) {
    __shared__ __align__(16) float shm[4160];
    int b = blockIdx.x, tid = threadIdx.x;

    if (b < 32) {
        float* dv   = shm;
        float* base = shm + 1024;
        float* WcA  = shm + 2048;
        float* WcB  = shm + 2080;
        for (int e = tid; e < 1024; e += 256) {
            int f = e >> 4, d = e & 15;
            if (f < 62) { dv[e] = emb[f * 32 + 16 + d] - emb[f * 32 + d]; base[e] = emb[f * 32 + d]; }
            else        { dv[e] = 0.f; base[e] = bc[e - 992]; }
        }
        if (tid < 32) { WcA[tid] = Wc[tid * 2]; WcB[tid] = Wc[tid * 2 + 1]; }
        __syncthreads();

        int w = tid >> 5, l = tid & 31;
        int j = b * 8 + w;
        const float4* wrow = (const float4*)(W1 + j * 1024);
        float cp = 0.f;
        #pragma unroll
        for (int r = 0; r < 8; r++) {
            int q = l + 32 * r;
            float4 wv = __ldg(wrow + q);
            int e0 = q * 4;
            float4 dvv = *(const float4*)(dv + e0);
            float4 bsv = *(const float4*)(base + e0);
            float pd = wv.x * dvv.x + wv.y * dvv.y + wv.z * dvv.z + wv.w * dvv.w;
            cp += wv.x * bsv.x + wv.y * bsv.y + wv.z * bsv.z + wv.w * bsv.w;
            pd += __shfl_xor_sync(0xffffffffu, pd, 1);
            pd += __shfl_xor_sync(0xffffffffu, pd, 2);
            float s62 = 0.f, s63 = 0.f;
            if (r == 7) {
                float p0 = 0.f, p1 = 0.f;
                if (l >= 24) {
                    int m0 = e0 - 992;
                    float4 wa = *(const float4*)(WcA + m0);
                    float4 wb = *(const float4*)(WcB + m0);
                    p0 = wv.x * wa.x + wv.y * wa.y + wv.z * wa.z + wv.w * wa.w;
                    p1 = wv.x * wb.x + wv.y * wb.y + wv.z * wb.z + wv.w * wb.w;
                }
                p0 += __shfl_xor_sync(0xffffffffu, p0, 1);
                p0 += __shfl_xor_sync(0xffffffffu, p0, 2);
                p0 += __shfl_xor_sync(0xffffffffu, p0, 4);
                p1 += __shfl_xor_sync(0xffffffffu, p1, 1);
                p1 += __shfl_xor_sync(0xffffffffu, p1, 2);
                p1 += __shfl_xor_sync(0xffffffffu, p1, 4);
                s62 = p0; s63 = p1;
            }
            float vnext = __shfl_sync(0xffffffffu, pd, (l + 4) & 31);
            int gidx = l >> 2;
            if ((l & 7) == 0) {
                float e0v = pd, e1v = vnext;
                if (r == 7 && gidx == 6) { e0v = s62; e1v = s63; }
                int p = (gidx >> 1) + 4 * r;
                int kt = p >> 3, reg = (p >> 2) & 1, tgx = p & 3;
                g_A1pack[((kt * 40 + (j >> 3)) * 32 + (j & 7) * 4 + tgx) * 2 + reg] =
                    pack_h2(e0v, e1v);
            }
        }
        #pragma unroll
        for (int o = 16; o; o >>= 1) cp += __shfl_xor_sync(0xffffffffu, cp, o);
        if (l == 0) g_c1[j] = cp + b1[j];

    } else if (b < 40) {
        int c = b - 32;
        float* w2s = shm;
        for (int q = tid; q < 1024; q += 256) {
            int row = q >> 3, f4 = q & 7;
            *(float4*)(w2s + row * 32 + f4 * 4) =
                __ldg((const float4*)(W2 + row * 256 + c * 32 + f4 * 4));
        }
        __syncthreads();
        for (int e = tid; e < 2048; e += 256) {
            int reg = e & 1, l2 = (e >> 1) & 31, nt = (e >> 6) & 15, itl = e >> 10;
            int gg = l2 >> 2, tgx = l2 & 3;
            int il = itl * 16 + reg * 8 + 2 * tgx;
            int k  = nt * 8 + gg;
            g_W2pack[c * 2048 + e] = pack_h2(w2s[k * 32 + il], w2s[k * 32 + il + 1]);
        }

    } else {
        int qb = b - 40;
        float (*v)[16] = (float(*)[16])shm;
        float* u  = shm + 1024;
        float* tS = shm + 1040;
        float* sS = shm + 1104;
        float* Rs = shm + 1168;
        for (int idx = tid; idx < 1024; idx += 256) {
            int f = idx >> 4, d = idx & 15;
            float val;
            if (f < 62)       val = emb[f * 32 + 16 + d] - emb[f * 32 + d];
            else if (f == 62) val = Wc[d * 2]     + Wc[(16 + d) * 2];
            else              val = Wc[d * 2 + 1] + Wc[(16 + d) * 2 + 1];
            v[f][d] = val;
        }
        if (tid < 16) {
            float s = bc[tid] + bc[16 + tid];
            for (int f = 0; f < 62; f++) s += emb[f * 32 + tid];
            u[tid] = s;
        }
        if (tid == 0) {
            float r = 0.f;
            for (int m = 0; m < 32; m++) r += Wc[m * 2] * Wc[m * 2 + 1];
            Rs[0] = r;
        }
        __syncthreads();
        if (tid < 64) {
            float t = 0.f, s = 0.f;
            if (tid < 62) {
                #pragma unroll
                for (int d = 0; d < 16; d++) { t += emb[tid * 32 + d] * v[tid][d]; s += v[tid][d] * v[tid][d]; }
            } else {
                int jc = tid - 62;
                for (int m = 0; m < 32; m++) { float wv = Wc[m * 2 + jc]; t += bc[m] * wv; s += wv * wv; }
            }
            tS[tid] = t; sS[tid] = s;
        }
        __syncthreads();
        int e = qb * 256 + tid;
        int gc = e >> 5, p = e & 31, f0 = 2 * p;
        float q2[2];
        #pragma unroll
        for (int h = 0; h < 2; h++) {
            int fr = f0 + h;
            if (fr == gc) {
                float uv = 0.f, vv = 0.f;
                #pragma unroll
                for (int d = 0; d < 16; d++) { uv += u[d] * v[fr][d]; vv += v[fr][d] * v[fr][d]; }
                q2[h] = uv - tS[fr] + 0.5f * (vv - sS[fr]) + Wf[fr];
            } else {
                float dp = 0.f;
                #pragma unroll
                for (int d = 0; d < 16; d++) dp += v[fr][d] * v[gc][d];
                float rr = ((fr == 62 && gc == 63) || (fr == 63 && gc == 62)) ? Rs[0] : 0.f;
                q2[h] = 0.5f * (dp - rr);
            }
        }
        int kt = p >> 3, reg = (p >> 2) & 1, tgx = p & 3;
        g_A1pack[((kt * 40 + 32 + (gc >> 3)) * 32 + (gc & 7) * 4 + tgx) * 2 + reg] =
            pack_h2(q2[0], q2[1]);
        if (qb == 0 && tid == 0) {
            float uu = 0.f;
            for (int d = 0; d < 16; d++) uu += u[d] * u[d];
            float e2 = 0.f;
            for (int f = 0; f < 62; f++)
                for (int d = 0; d < 16; d++) { float ev = emb[f * 32 + d]; e2 += ev * ev; }
            for (int m = 0; m < 32; m++) e2 += bc[m] * bc[m];
            g_c0[0] = bf[0] + 0.5f * (uu - e2);
        }
    }
}

// =============== fused main kernel: B-frags from L2, occ 4 ===============
__global__ __launch_bounds__(256, 4) void deepfm_main(
    const float* __restrict__ x, const float* __restrict__ b2, float* __restrict__ out) {
    extern __shared__ unsigned smu[];
    __half* xs = (__half*)smu;              // [64][72]
    __half* h1 = (__half*)(smu + OFF_H1);   // [64][264]

    const int tid = threadIdx.x;
    const int b0  = blockIdx.x * 64;

    // ---- stage x (fp32 -> fp16) ----
    {
        int s = tid >> 2, q = tid & 3;
        const float4* xr = (const float4*)(x + (size_t)(b0 + s) * 64 + q * 16);
        float4 v0 = __ldg(xr), v1 = __ldg(xr + 1), v2 = __ldg(xr + 2), v3 = __ldg(xr + 3);
        __half2* dst = (__half2*)(xs + s * 72 + q * 16);
        dst[0] = __floats2half2_rn(v0.x, v0.y); dst[1] = __floats2half2_rn(v0.z, v0.w);
        dst[2] = __floats2half2_rn(v1.x, v1.y); dst[3] = __floats2half2_rn(v1.z, v1.w);
        dst[4] = __floats2half2_rn(v2.x, v2.y); dst[5] = __floats2half2_rn(v2.z, v2.w);
        dst[6] = __floats2half2_rn(v3.x, v3.y); dst[7] = __floats2half2_rn(v3.z, v3.w);
    }
    __syncthreads();

    const int w = tid >> 5, l = tid & 31, g = l >> 2, tg = l & 3;
    const int mh = w & 1, nq = w >> 1;           // 2 m-halves x 4 n-quarters
    const int lrow = l & 15, lcol = l >> 4;
    const int rbase = mh * 32;

    unsigned xs_lm0 = (unsigned)__cvta_generic_to_shared(xs + (rbase + lrow) * 72 + lcol * 8);
    unsigned xs_lm1 = xs_lm0 + 16 * 72 * 2;
    unsigned h1_lm0 = (unsigned)__cvta_generic_to_shared(h1 + (rbase + lrow) * 264 + lcol * 8);
    unsigned h1_lm1 = h1_lm0 + 16 * 264 * 2;

    // ---- GEMM1: z[64 x 320] = x @ [A1 | Q], B-frags from L2 with prefetch ----
    float fmd[2][2] = {{0.f, 0.f}, {0.f, 0.f}};
    const int ntb = nq * 10;
    #pragma unroll 1
    for (int pass = 0; pass < 2; pass++) {
        int nt0 = ntb + pass * 5;
        const uint2* bbase = (const uint2*)g_A1pack + nt0 * 32 + l;
        uint2 bc_[5];
        #pragma unroll
        for (int t = 0; t < 5; t++) bc_[t] = __ldg(bbase + t * 32);

        float acc[2][5][4];
        #pragma unroll
        for (int t = 0; t < 5; t++) {
            int j0 = (nt0 + t) * 8;
            float c0v = 0.f, c1v = 0.f;
            if (j0 < 256) { float2 cc = __ldg((const float2*)(g_c1 + j0 + 2 * tg)); c0v = cc.x; c1v = cc.y; }
            acc[0][t][0] = c0v; acc[0][t][1] = c1v; acc[0][t][2] = c0v; acc[0][t][3] = c1v;
            acc[1][t][0] = c0v; acc[1][t][1] = c1v; acc[1][t][2] = c0v; acc[1][t][3] = c1v;
        }
        #pragma unroll
        for (int kt = 0; kt < 4; kt++) {
            uint2 bn_[5];
            if (kt < 3) {
                const uint2* bp = bbase + (kt + 1) * 40 * 32;
                #pragma unroll
                for (int t = 0; t < 5; t++) bn_[t] = __ldg(bp + t * 32);
            }
            unsigned am0[4], am1[4];
            ldsm_x4(am0[0], am0[1], am0[2], am0[3], xs_lm0 + kt * 32);
            ldsm_x4(am1[0], am1[1], am1[2], am1[3], xs_lm1 + kt * 32);
            #pragma unroll
            for (int t = 0; t < 5; t++) {
                mma_fp16(acc[0][t], am0[0], am0[1], am0[2], am0[3], bc_[t].x, bc_[t].y);
                mma_fp16(acc[1][t], am1[0], am1[1], am1[2], am1[3], bc_[t].x, bc_[t].y);
            }
            if (kt < 3) {
                #pragma unroll
                for (int t = 0; t < 5; t++) bc_[t] = bn_[t];
            }
        }
        #pragma unroll
        for (int t = 0; t < 5; t++) {
            int j0 = (nt0 + t) * 8;
            #pragma unroll
            for (int mt = 0; mt < 2; mt++) {
                int r0 = rbase + mt * 16 + g;
                if (j0 < 256) {
                    *(__half2*)(h1 + r0 * 264 + j0 + 2 * tg) =
                        __floats2half2_rn(fmaxf(acc[mt][t][0], 0.f), fmaxf(acc[mt][t][1], 0.f));
                    *(__half2*)(h1 + (r0 + 8) * 264 + j0 + 2 * tg) =
                        __floats2half2_rn(fmaxf(acc[mt][t][2], 0.f), fmaxf(acc[mt][t][3], 0.f));
                } else {
                    int fo = j0 - 256;
                    float2 xf0 = __half22float2(*(__half2*)(xs + r0 * 72 + fo + 2 * tg));
                    float2 xf1 = __half22float2(*(__half2*)(xs + (r0 + 8) * 72 + fo + 2 * tg));
                    fmd[mt][0] += xf0.x * acc[mt][t][0] + xf0.y * acc[mt][t][1];
                    fmd[mt][1] += xf1.x * acc[mt][t][2] + xf1.y * acc[mt][t][3];
                }
            }
        }
    }
    if (nq == 3) {   // FM output
        #pragma unroll
        for (int mt = 0; mt < 2; mt++) {
            #pragma unroll
            for (int i = 0; i < 2; i++) {
                fmd[mt][i] += __shfl_xor_sync(0xffffffffu, fmd[mt][i], 1);
                fmd[mt][i] += __shfl_xor_sync(0xffffffffu, fmd[mt][i], 2);
            }
        }
        if (tg == 0) {
            float C0 = __ldg(&g_c0[0]);
            #pragma unroll
            for (int mt = 0; mt < 2; mt++) {
                int r0 = rbase + mt * 16 + g;
                out[(size_t)(b0 + r0) * 129]     = C0 + fmd[mt][0];
                out[(size_t)(b0 + r0 + 8) * 129] = C0 + fmd[mt][1];
            }
        }
    }

    // ---- GEMM2 prologue hoisted ABOVE the h1 barrier (no h1 dependence) ----
    const uint2* wbase = (const uint2*)g_W2pack + nq * 4 * 32 + l;
    uint2 wc_[4];
    #pragma unroll
    for (int t = 0; t < 4; t++) wc_[t] = __ldg(wbase + t * 32);
    float acc2[2][4][4];
    #pragma unroll
    for (int t = 0; t < 4; t++) {
        int k0 = nq * 32 + t * 8;
        float2 bb = __ldg((const float2*)(b2 + k0 + 2 * tg));
        acc2[0][t][0] = bb.x; acc2[0][t][1] = bb.y; acc2[0][t][2] = bb.x; acc2[0][t][3] = bb.y;
        acc2[1][t][0] = bb.x; acc2[1][t][1] = bb.y; acc2[1][t][2] = bb.x; acc2[1][t][3] = bb.y;
    }
    __syncthreads();   // h1 complete

    // ---- GEMM2: out[:,1:] = relu(h1 @ W2T + b2), B-frags from L2 with prefetch ----
    #pragma unroll
    for (int it = 0; it < 16; it++) {
        uint2 wn_[4];
        if (it < 15) {
            const uint2* wp = wbase + (it + 1) * 16 * 32;
            #pragma unroll
            for (int t = 0; t < 4; t++) wn_[t] = __ldg(wp + t * 32);
        }
        unsigned aa0[4], aa1[4];
        ldsm_x4(aa0[0], aa0[1], aa0[2], aa0[3], h1_lm0 + it * 32);
        ldsm_x4(aa1[0], aa1[1], aa1[2], aa1[3], h1_lm1 + it * 32);
        #pragma unroll
        for (int t = 0; t < 4; t++) {
            mma_fp16(acc2[0][t], aa0[0], aa0[1], aa0[2], aa0[3], wc_[t].x, wc_[t].y);
            mma_fp16(acc2[1][t], aa1[0], aa1[1], aa1[2], aa1[3], wc_[t].x, wc_[t].y);
        }
        if (it < 15) {
            #pragma unroll
            for (int t = 0; t < 4; t++) wc_[t] = wn_[t];
        }
    }
    #pragma unroll
    for (int mt = 0; mt < 2; mt++) {
        #pragma unroll
        for (int t = 0; t < 4; t++) {
            int k0 = nq * 32 + t * 8 + 2 * tg;
            int r0 = rbase + mt * 16 + g;
            size_t o0 = (size_t)(b0 + r0) * 129 + 1 + k0;
            size_t o1 = (size_t)(b0 + r0 + 8) * 129 + 1 + k0;
            out[o0]     = fmaxf(acc2[mt][t][0], 0.f);
            out[o0 + 1] = fmaxf(acc2[mt][t][1], 0.f);
            out[o1]     = fmaxf(acc2[mt][t][2], 0.f);
            out[o1 + 1] = fmaxf(acc2[mt][t][3], 0.f);
        }
    }
}

// ---------------- launch ----------------
extern "C" void kernel_launch(void* const* d_in, const int* in_sizes, int n_in,
                              void* d_out, int out_size) {
    const float* x   = (const float*)d_in[0];
    const float* emb = (const float*)d_in[1];
    const float* Wc  = (const float*)d_in[2];
    const float* bc  = (const float*)d_in[3];
    const float* Wf  = (const float*)d_in[4];
    const float* bf  = (const float*)d_in[5];
    const float* W1  = (const float*)d_in[6];
    const float* b1  = (const float*)d_in[7];
    const float* W2  = (const float*)d_in[8];
    const float* b2  = (const float*)d_in[9];
    float* out = (float*)d_out;

    prep_all<<<48, 256>>>(emb, Wc, bc, Wf, bf, W1, b1, W2);
    cudaFuncSetAttribute(deepfm_main, cudaFuncAttributeMaxDynamicSharedMemorySize, SMEM_BYTES);
    deepfm_main<<<1024, 256, SMEM_BYTES>>>(x, b2, out);
}

// round 9
// speedup vs baseline: 1.0781x; 1.0437x over previous
#include <cuda_runtime.h>
#include <cuda_fp16.h>

// ---------------- smem layout (u32 units) ----------------
#define OFF_H1  2304                 // xs: 64x72 halves = 2304 u32
#define SMEM_U32 10752               // h1: 64x264 halves = 8448 u32
#define SMEM_BYTES (SMEM_U32 * 4)    // 43008

// device scratch
__device__ unsigned g_A1pack[10240];   // GEMM1 B frags (fp16x2): [A1 | Q], 320 cols
__device__ unsigned g_W2pack[16384];   // GEMM2 B frags (fp16x2)
__device__ float    g_c1[256];
__device__ float    g_c0[1];

__device__ __forceinline__ unsigned pack_h2(float a, float b) {
    __half2 h = __floats2half2_rn(a, b);
    return *(unsigned*)&h;
}
__device__ __forceinline__ void mma_fp16(float* c, unsigned a0, unsigned a1,
                                         unsigned a2, unsigned a3,
                                         unsigned b0, unsigned b1) {
    asm volatile("mma.sync.aligned.m16n8k16.row.col.f32.f16.f16.f32 "
                 "{%0,%1,%2,%3}, {%4,%5,%6,%7}, {%8,%9}, {%0,%1,%2,%3};"
                 : "+f"(c[0]), "+f"(c[1]), "+f"(c[2]), "+f"(c[3])
                 : "r"(a0), "r"(a1), "r"(a2), "r"(a3), "r"(b0), "r"(b1));
}
__device__ __forceinline__ void ldsm_x4(unsigned& r0, unsigned& r1, unsigned& r2,
                                        unsigned& r3, unsigned saddr) {
    asm volatile("ldmatrix.sync.aligned.m8n8.x4.shared.b16 {%0,%1,%2,%3}, [%4];"
                 : "=r"(r0), "=r"(r1), "=r"(r2), "=r"(r3) : "r"(saddr));
}

// =============== prep kernel: 80 blocks ===============
// b 0..63 : A1 frags + c1   (2 warps per j-row; 4 rows/block)
// b 64..71: W2 frags
// b 72..79: Q frags + C0
__global__ void prep_all(const float* __restrict__ emb, const float* __restrict__ Wc,
                         const float* __restrict__ bc,  const float* __restrict__ Wf,
                         const float* __restrict__ bf,  const float* __restrict__ W1,
                         const float* __restrict__ b1,  const float* __restrict__ W2) {
    __shared__ __align__(16) float shm[4160];
    int b = blockIdx.x, tid = threadIdx.x;

    if (b < 64) {
        float* dv   = shm;          // [1024]
        float* base = shm + 1024;   // [1024]
        float* WcA  = shm + 2048;   // [32]
        float* WcB  = shm + 2080;   // [32]
        float* cpsh = shm + 2112;   // [8]
        for (int e = tid; e < 1024; e += 256) {
            int f = e >> 4, d = e & 15;
            if (f < 62) { dv[e] = emb[f * 32 + 16 + d] - emb[f * 32 + d]; base[e] = emb[f * 32 + d]; }
            else        { dv[e] = 0.f; base[e] = bc[e - 992]; }
        }
        if (tid < 32) { WcA[tid] = Wc[tid * 2]; WcB[tid] = Wc[tid * 2 + 1]; }
        __syncthreads();

        int w = tid >> 5, l = tid & 31;
        int j  = b * 4 + (w >> 1);    // 4 rows per block
        int wh = w & 1;               // row half: r in [4wh, 4wh+4)
        const float4* wrow = (const float4*)(W1 + j * 1024);
        float cp = 0.f;
        #pragma unroll
        for (int rr = 0; rr < 4; rr++) {
            int r = wh * 4 + rr;
            int q = l + 32 * r;
            float4 wv = __ldg(wrow + q);
            int e0 = q * 4;
            float4 dvv = *(const float4*)(dv + e0);
            float4 bsv = *(const float4*)(base + e0);
            float pd = wv.x * dvv.x + wv.y * dvv.y + wv.z * dvv.z + wv.w * dvv.w;
            cp += wv.x * bsv.x + wv.y * bsv.y + wv.z * bsv.z + wv.w * bsv.w;
            pd += __shfl_xor_sync(0xffffffffu, pd, 1);
            pd += __shfl_xor_sync(0xffffffffu, pd, 2);
            float s62 = 0.f, s63 = 0.f;
            if (r == 7) {   // cont features 62/63 use all 32 W1 tail entries
                float p0 = 0.f, p1 = 0.f;
                if (l >= 24) {
                    int m0 = e0 - 992;
                    float4 wa = *(const float4*)(WcA + m0);
                    float4 wb = *(const float4*)(WcB + m0);
                    p0 = wv.x * wa.x + wv.y * wa.y + wv.z * wa.z + wv.w * wa.w;
                    p1 = wv.x * wb.x + wv.y * wb.y + wv.z * wb.z + wv.w * wb.w;
                }
                p0 += __shfl_xor_sync(0xffffffffu, p0, 1);
                p0 += __shfl_xor_sync(0xffffffffu, p0, 2);
                p0 += __shfl_xor_sync(0xffffffffu, p0, 4);
                p1 += __shfl_xor_sync(0xffffffffu, p1, 1);
                p1 += __shfl_xor_sync(0xffffffffu, p1, 2);
                p1 += __shfl_xor_sync(0xffffffffu, p1, 4);
                s62 = p0; s63 = p1;
            }
            float vnext = __shfl_sync(0xffffffffu, pd, (l + 4) & 31);
            int gidx = l >> 2;
            if ((l & 7) == 0) {
                float e0v = pd, e1v = vnext;
                if (r == 7 && gidx == 6) { e0v = s62; e1v = s63; }
                int p = (gidx >> 1) + 4 * r;           // feature-pair index f/2
                int kt = p >> 3, reg = (p >> 2) & 1, tgx = p & 3;
                g_A1pack[((kt * 40 + (j >> 3)) * 32 + (j & 7) * 4 + tgx) * 2 + reg] =
                    pack_h2(e0v, e1v);
            }
        }
        #pragma unroll
        for (int o = 16; o; o >>= 1) cp += __shfl_xor_sync(0xffffffffu, cp, o);
        if (l == 0) cpsh[w] = cp;
        __syncthreads();
        if (tid < 4) {
            int jj = b * 4 + tid;
            g_c1[jj] = cpsh[2 * tid] + cpsh[2 * tid + 1] + b1[jj];
        }

    } else if (b < 72) {
        int c = b - 64;
        float* w2s = shm;   // [128][32] cols [32c, 32c+32)
        for (int q = tid; q < 1024; q += 256) {
            int row = q >> 3, f4 = q & 7;
            *(float4*)(w2s + row * 32 + f4 * 4) =
                __ldg((const float4*)(W2 + row * 256 + c * 32 + f4 * 4));
        }
        __syncthreads();
        for (int e = tid; e < 2048; e += 256) {
            int reg = e & 1, l2 = (e >> 1) & 31, nt = (e >> 6) & 15, itl = e >> 10;
            int gg = l2 >> 2, tgx = l2 & 3;
            int il = itl * 16 + reg * 8 + 2 * tgx;
            int k  = nt * 8 + gg;
            g_W2pack[c * 2048 + e] = pack_h2(w2s[k * 32 + il], w2s[k * 32 + il + 1]);
        }

    } else {
        int qb = b - 72;
        float (*v)[16] = (float(*)[16])shm;
        float* u  = shm + 1024;
        float* tS = shm + 1040;
        float* sS = shm + 1104;
        float* Rs = shm + 1168;
        for (int idx = tid; idx < 1024; idx += 256) {
            int f = idx >> 4, d = idx & 15;
            float val;
            if (f < 62)       val = emb[f * 32 + 16 + d] - emb[f * 32 + d];
            else if (f == 62) val = Wc[d * 2]     + Wc[(16 + d) * 2];
            else              val = Wc[d * 2 + 1] + Wc[(16 + d) * 2 + 1];
            v[f][d] = val;
        }
        if (tid < 16) {
            float s = bc[tid] + bc[16 + tid];
            for (int f = 0; f < 62; f++) s += emb[f * 32 + tid];
            u[tid] = s;
        }
        if (tid == 0) {
            float r = 0.f;
            for (int m = 0; m < 32; m++) r += Wc[m * 2] * Wc[m * 2 + 1];
            Rs[0] = r;
        }
        __syncthreads();
        if (tid < 64) {
            float t = 0.f, s = 0.f;
            if (tid < 62) {
                #pragma unroll
                for (int d = 0; d < 16; d++) { t += emb[tid * 32 + d] * v[tid][d]; s += v[tid][d] * v[tid][d]; }
            } else {
                int jc = tid - 62;
                for (int m = 0; m < 32; m++) { float wv = Wc[m * 2 + jc]; t += bc[m] * wv; s += wv * wv; }
            }
            tS[tid] = t; sS[tid] = s;
        }
        __syncthreads();
        int e = qb * 256 + tid;
        int gc = e >> 5, p = e & 31, f0 = 2 * p;
        float q2[2];
        #pragma unroll
        for (int h = 0; h < 2; h++) {
            int fr = f0 + h;
            if (fr == gc) {
                float uv = 0.f, vv = 0.f;
                #pragma unroll
                for (int d = 0; d < 16; d++) { uv += u[d] * v[fr][d]; vv += v[fr][d] * v[fr][d]; }
                q2[h] = uv - tS[fr] + 0.5f * (vv - sS[fr]) + Wf[fr];
            } else {
                float dp = 0.f;
                #pragma unroll
                for (int d = 0; d < 16; d++) dp += v[fr][d] * v[gc][d];
                float rr = ((fr == 62 && gc == 63) || (fr == 63 && gc == 62)) ? Rs[0] : 0.f;
                q2[h] = 0.5f * (dp - rr);
            }
        }
        int kt = p >> 3, reg = (p >> 2) & 1, tgx = p & 3;
        g_A1pack[((kt * 40 + 32 + (gc >> 3)) * 32 + (gc & 7) * 4 + tgx) * 2 + reg] =
            pack_h2(q2[0], q2[1]);
        if (qb == 0 && tid == 0) {
            float uu = 0.f;
            for (int d = 0; d < 16; d++) uu += u[d] * u[d];
            float e2 = 0.f;
            for (int f = 0; f < 62; f++)
                for (int d = 0; d < 16; d++) { float ev = emb[f * 32 + d]; e2 += ev * ev; }
            for (int m = 0; m < 32; m++) e2 += bc[m] * bc[m];
            g_c0[0] = bf[0] + 0.5f * (uu - e2);
        }
    }
}

// =============== fused main kernel: R6-exact (proven 41.2us) ===============
__global__ __launch_bounds__(256, 3) void deepfm_main(
    const float* __restrict__ x, const float* __restrict__ b2, float* __restrict__ out) {
    extern __shared__ unsigned smu[];
    __half* xs = (__half*)smu;              // [64][72]
    __half* h1 = (__half*)(smu + OFF_H1);   // [64][264]

    const int tid = threadIdx.x;
    const int b0  = blockIdx.x * 64;

    // ---- stage x (fp32 -> fp16) ----
    {
        int s = tid >> 2, q = tid & 3;
        const float4* xr = (const float4*)(x + (size_t)(b0 + s) * 64 + q * 16);
        float4 v0 = __ldg(xr), v1 = __ldg(xr + 1), v2 = __ldg(xr + 2), v3 = __ldg(xr + 3);
        __half2* dst = (__half2*)(xs + s * 72 + q * 16);
        dst[0] = __floats2half2_rn(v0.x, v0.y); dst[1] = __floats2half2_rn(v0.z, v0.w);
        dst[2] = __floats2half2_rn(v1.x, v1.y); dst[3] = __floats2half2_rn(v1.z, v1.w);
        dst[4] = __floats2half2_rn(v2.x, v2.y); dst[5] = __floats2half2_rn(v2.z, v2.w);
        dst[6] = __floats2half2_rn(v3.x, v3.y); dst[7] = __floats2half2_rn(v3.z, v3.w);
    }
    __syncthreads();

    const int w = tid >> 5, l = tid & 31, g = l >> 2, tg = l & 3;
    const int mh = w & 1, nq = w >> 1;           // 2 m-halves x 4 n-quarters
    const int lrow = l & 15, lcol = l >> 4;
    const int rbase = mh * 32;

    unsigned xs_lm0 = (unsigned)__cvta_generic_to_shared(xs + (rbase + lrow) * 72 + lcol * 8);
    unsigned xs_lm1 = xs_lm0 + 16 * 72 * 2;
    unsigned h1_lm0 = (unsigned)__cvta_generic_to_shared(h1 + (rbase + lrow) * 264 + lcol * 8);
    unsigned h1_lm1 = h1_lm0 + 16 * 264 * 2;

    // ---- GEMM1: z[64 x 320] = x @ [A1 | Q], B-frags from L2 with prefetch ----
    float fmd[2][2] = {{0.f, 0.f}, {0.f, 0.f}};
    const int ntb = nq * 10;
    #pragma unroll 1
    for (int pass = 0; pass < 2; pass++) {
        int nt0 = ntb + pass * 5;
        const uint2* bbase = (const uint2*)g_A1pack + nt0 * 32 + l;
        uint2 bc_[5];
        #pragma unroll
        for (int t = 0; t < 5; t++) bc_[t] = __ldg(bbase + t * 32);

        float acc[2][5][4];
        #pragma unroll
        for (int t = 0; t < 5; t++) {
            int j0 = (nt0 + t) * 8;
            float c0v = 0.f, c1v = 0.f;
            if (j0 < 256) { float2 cc = __ldg((const float2*)(g_c1 + j0 + 2 * tg)); c0v = cc.x; c1v = cc.y; }
            acc[0][t][0] = c0v; acc[0][t][1] = c1v; acc[0][t][2] = c0v; acc[0][t][3] = c1v;
            acc[1][t][0] = c0v; acc[1][t][1] = c1v; acc[1][t][2] = c0v; acc[1][t][3] = c1v;
        }
        #pragma unroll
        for (int kt = 0; kt < 4; kt++) {
            uint2 bn_[5];
            if (kt < 3) {
                const uint2* bp = bbase + (kt + 1) * 40 * 32;
                #pragma unroll
                for (int t = 0; t < 5; t++) bn_[t] = __ldg(bp + t * 32);
            }
            unsigned am0[4], am1[4];
            ldsm_x4(am0[0], am0[1], am0[2], am0[3], xs_lm0 + kt * 32);
            ldsm_x4(am1[0], am1[1], am1[2], am1[3], xs_lm1 + kt * 32);
            #pragma unroll
            for (int t = 0; t < 5; t++) {
                mma_fp16(acc[0][t], am0[0], am0[1], am0[2], am0[3], bc_[t].x, bc_[t].y);
                mma_fp16(acc[1][t], am1[0], am1[1], am1[2], am1[3], bc_[t].x, bc_[t].y);
            }
            if (kt < 3) {
                #pragma unroll
                for (int t = 0; t < 5; t++) bc_[t] = bn_[t];
            }
        }
        #pragma unroll
        for (int t = 0; t < 5; t++) {
            int j0 = (nt0 + t) * 8;
            #pragma unroll
            for (int mt = 0; mt < 2; mt++) {
                int r0 = rbase + mt * 16 + g;
                if (j0 < 256) {
                    *(__half2*)(h1 + r0 * 264 + j0 + 2 * tg) =
                        __floats2half2_rn(fmaxf(acc[mt][t][0], 0.f), fmaxf(acc[mt][t][1], 0.f));
                    *(__half2*)(h1 + (r0 + 8) * 264 + j0 + 2 * tg) =
                        __floats2half2_rn(fmaxf(acc[mt][t][2], 0.f), fmaxf(acc[mt][t][3], 0.f));
                } else {
                    int fo = j0 - 256;
                    float2 xf0 = __half22float2(*(__half2*)(xs + r0 * 72 + fo + 2 * tg));
                    float2 xf1 = __half22float2(*(__half2*)(xs + (r0 + 8) * 72 + fo + 2 * tg));
                    fmd[mt][0] += xf0.x * acc[mt][t][0] + xf0.y * acc[mt][t][1];
                    fmd[mt][1] += xf1.x * acc[mt][t][2] + xf1.y * acc[mt][t][3];
                }
            }
        }
    }
    if (nq == 3) {   // FM output
        #pragma unroll
        for (int mt = 0; mt < 2; mt++) {
            #pragma unroll
            for (int i = 0; i < 2; i++) {
                fmd[mt][i] += __shfl_xor_sync(0xffffffffu, fmd[mt][i], 1);
                fmd[mt][i] += __shfl_xor_sync(0xffffffffu, fmd[mt][i], 2);
            }
        }
        if (tg == 0) {
            float C0 = __ldg(&g_c0[0]);
            #pragma unroll
            for (int mt = 0; mt < 2; mt++) {
                int r0 = rbase + mt * 16 + g;
                out[(size_t)(b0 + r0) * 129]     = C0 + fmd[mt][0];
                out[(size_t)(b0 + r0 + 8) * 129] = C0 + fmd[mt][1];
            }
        }
    }
    __syncthreads();   // h1 complete

    // ---- GEMM2: out[:,1:] = relu(h1 @ W2T + b2), B-frags from L2 with prefetch ----
    float acc2[2][4][4];
    #pragma unroll
    for (int t = 0; t < 4; t++) {
        int k0 = nq * 32 + t * 8;
        float2 bb = __ldg((const float2*)(b2 + k0 + 2 * tg));
        acc2[0][t][0] = bb.x; acc2[0][t][1] = bb.y; acc2[0][t][2] = bb.x; acc2[0][t][3] = bb.y;
        acc2[1][t][0] = bb.x; acc2[1][t][1] = bb.y; acc2[1][t][2] = bb.x; acc2[1][t][3] = bb.y;
    }
    {
        const uint2* wbase = (const uint2*)g_W2pack + nq * 4 * 32 + l;
        uint2 wc_[4];
        #pragma unroll
        for (int t = 0; t < 4; t++) wc_[t] = __ldg(wbase + t * 32);
        #pragma unroll
        for (int it = 0; it < 16; it++) {
            uint2 wn_[4];
            if (it < 15) {
                const uint2* wp = wbase + (it + 1) * 16 * 32;
                #pragma unroll
                for (int t = 0; t < 4; t++) wn_[t] = __ldg(wp + t * 32);
            }
            unsigned aa0[4], aa1[4];
            ldsm_x4(aa0[0], aa0[1], aa0[2], aa0[3], h1_lm0 + it * 32);
            ldsm_x4(aa1[0], aa1[1], aa1[2], aa1[3], h1_lm1 + it * 32);
            #pragma unroll
            for (int t = 0; t < 4; t++) {
                mma_fp16(acc2[0][t], aa0[0], aa0[1], aa0[2], aa0[3], wc_[t].x, wc_[t].y);
                mma_fp16(acc2[1][t], aa1[0], aa1[1], aa1[2], aa1[3], wc_[t].x, wc_[t].y);
            }
            if (it < 15) {
                #pragma unroll
                for (int t = 0; t < 4; t++) wc_[t] = wn_[t];
            }
        }
    }
    #pragma unroll
    for (int mt = 0; mt < 2; mt++) {
        #pragma unroll
        for (int t = 0; t < 4; t++) {
            int k0 = nq * 32 + t * 8 + 2 * tg;
            int r0 = rbase + mt * 16 + g;
            size_t o0 = (size_t)(b0 + r0) * 129 + 1 + k0;
            size_t o1 = (size_t)(b0 + r0 + 8) * 129 + 1 + k0;
            out[o0]     = fmaxf(acc2[mt][t][0], 0.f);
            out[o0 + 1] = fmaxf(acc2[mt][t][1], 0.f);
            out[o1]     = fmaxf(acc2[mt][t][2], 0.f);
            out[o1 + 1] = fmaxf(acc2[mt][t][3], 0.f);
        }
    }
}

// ---------------- launch ----------------
extern "C" void kernel_launch(void* const* d_in, const int* in_sizes, int n_in,
                              void* d_out, int out_size) {
    const float* x   = (const float*)d_in[0];
    const float* emb = (const float*)d_in[1];
    const float* Wc  = (const float*)d_in[2];
    const float* bc  = (const float*)d_in[3];
    const float* Wf  = (const float*)d_in[4];
    const float* bf  = (const float*)d_in[5];
    const float* W1  = (const float*)d_in[6];
    const float* b1  = (const float*)d_in[7];
    const float* W2  = (const float*)d_in[8];
    const float* b2  = (const float*)d_in[9];
    float* out = (float*)d_out;

    prep_all<<<80, 256>>>(emb, Wc, bc, Wf, bf, W1, b1, W2);
    cudaFuncSetAttribute(deepfm_main, cudaFuncAttributeMaxDynamicSharedMemorySize, SMEM_BYTES);
    deepfm_main<<<1024, 256, SMEM_BYTES>>>(x, b2, out);
}